// round 9
// baseline (speedup 1.0000x reference)
#include <cuda_runtime.h>
#include <cstddef>

// Problem constants (fixed by the dataset)
#define BATCH   64
#define NNODE   16384              // nodes per sample
#define BNODES  1048576            // BATCH * NNODE
#define EDGES   8388608
#define COUT    8
#define DIM     128
#define BOUT    16

// edge bucketing
#define BSHIFT   13                // nodes per bucket = 8192
#define BNPB     (1 << BSHIFT)     // 8192
#define NBUCK    (BNODES / BNPB)   // 128
#define BUCKCAP  69632             // 65536 mean + 16 sigma
#define EPC      2048              // edges per sort CTA
#define SORT_CTAS (EDGES / EPC)    // 4096
#define ACC_SPLIT 4                // CTAs per bucket in accumulation
#define ACC_CTAS (NBUCK * ACC_SPLIT)  // 512

// fc1 GEMM tiling
#define NB_FC1        1024
#define NODES_PER_BLK 16

// -------- device scratch (no allocations allowed) --------
__device__ float g_deg[BNODES];
__device__ float g_dinv[BNODES];
__device__ float g_u[BNODES];                      // dinv * x
__device__ float g_S[BNODES];                      // scatter accumulator
__device__ float g_part[(size_t)NB_FC1 * BATCH * DIM];   // 32 MB fc1 partials
__device__ float g_h1[BATCH * DIM];

// sorted edge storage (bucketed by destination row)
__device__ unsigned short s_lrow[(size_t)NBUCK * BUCKCAP];  // row & (BNPB-1)
__device__ int            s_col [(size_t)NBUCK * BUCKCAP];
__device__ float          s_ea  [(size_t)NBUCK * BUCKCAP];
__device__ int            g_cursor[NBUCK];

// -------- f32x2 packed-FMA helpers --------
__device__ __forceinline__ unsigned long long pk2(float lo, float hi) {
    unsigned long long r;
    asm("mov.b64 %0, {%1,%2};" : "=l"(r) : "f"(lo), "f"(hi));
    return r;
}
__device__ __forceinline__ unsigned long long dup2(float v) { return pk2(v, v); }
__device__ __forceinline__ void fma2(unsigned long long& d, unsigned long long a,
                                     unsigned long long b) {
    asm("fma.rn.f32x2 %0, %1, %2, %0;" : "+l"(d) : "l"(a), "l"(b));
}
__device__ __forceinline__ void unpk2(unsigned long long v, float& lo, float& hi) {
    asm("mov.b64 {%0,%1}, %2;" : "=f"(lo), "=f"(hi) : "l"(v));
}

__device__ __forceinline__ float lrelu(float v) { return v > 0.f ? v : 0.01f * v; }

// -------- kernels --------

// zero g_deg and bucket cursors
__global__ void k_init() {
    int i = blockIdx.x * blockDim.x + threadIdx.x;   // < BNODES/4
    ((float4*)g_deg)[i] = make_float4(0.f, 0.f, 0.f, 0.f);
    if (blockIdx.x == 0 && threadIdx.x < NBUCK) g_cursor[threadIdx.x] = 0;
}

// coarse bucket sort of edges by destination (row >> BSHIFT)
__global__ __launch_bounds__(256) void k_sort(const int* __restrict__ row,
                                              const int* __restrict__ col,
                                              const float* __restrict__ ea) {
    __shared__ int cnt[NBUCK], lbase[NBUCK], gdst[NBUCK], lcur[NBUCK];
    __shared__ unsigned char  bkt_in[EPC];
    __shared__ unsigned short lrow_in[EPC];
    __shared__ unsigned short lrowS[EPC];
    __shared__ unsigned char  bktS[EPC];
    __shared__ int            colS[EPC];
    __shared__ float          eaS[EPC];

    int tid  = threadIdx.x;
    int base = blockIdx.x * EPC;
    if (tid < NBUCK) { cnt[tid] = 0; lcur[tid] = 0; }
    __syncthreads();

    // P1: bucket histogram + cache local row bits
#pragma unroll
    for (int j = 0; j < EPC / 256; j++) {
        int i = tid + j * 256;
        int r = row[base + i];
        int b = r >> BSHIFT;
        bkt_in[i]  = (unsigned char)b;
        lrow_in[i] = (unsigned short)(r & (BNPB - 1));
        atomicAdd(&cnt[b], 1);
    }
    __syncthreads();

    // P2: serial exclusive scan (128 entries) + global run reservation
    if (tid == 0) {
        int acc = 0;
        for (int b = 0; b < NBUCK; b++) { lbase[b] = acc; acc += cnt[b]; }
    }
    __syncthreads();
    if (tid < NBUCK) gdst[tid] = atomicAdd(&g_cursor[tid], cnt[tid]);
    __syncthreads();

    // P3: scatter into smem staging in bucket order
#pragma unroll
    for (int j = 0; j < EPC / 256; j++) {
        int i = tid + j * 256;
        int b = bkt_in[i];
        int slot = atomicAdd(&lcur[b], 1) + lbase[b];
        colS[slot]  = col[base + i];
        eaS[slot]   = ea[base + i];
        lrowS[slot] = lrow_in[i];
        bktS[slot]  = (unsigned char)b;
    }
    __syncthreads();

    // P4: coalesced run copy-out
#pragma unroll
    for (int j = 0; j < EPC / 256; j++) {
        int s = tid + j * 256;
        int b = bktS[s];
        size_t p = (size_t)b * BUCKCAP + gdst[b] + (s - lbase[b]);
        s_lrow[p] = lrowS[s];
        s_col[p]  = colS[s];
        s_ea[p]   = eaS[s];
    }
}

// deg accumulation from sorted edges via smem, coalesced RED merge
__global__ __launch_bounds__(256) void k_sdeg() {
    __shared__ float acc[BNPB];     // 32 KB
    int b   = blockIdx.x / ACC_SPLIT;
    int q   = blockIdx.x % ACC_SPLIT;
    int tid = threadIdx.x;
    for (int i = tid; i < BNPB; i += 256) acc[i] = 0.f;
    __syncthreads();
    int n  = g_cursor[b];
    int e0 = (q * n) / ACC_SPLIT, e1 = ((q + 1) * n) / ACC_SPLIT;
    size_t bb = (size_t)b * BUCKCAP;
    for (int e = e0 + tid; e < e1; e += 256)
        atomicAdd(&acc[s_lrow[bb + e]], s_ea[bb + e]);
    __syncthreads();
    float* dst = g_deg + ((size_t)b << BSHIFT);
    for (int i = tid; i < BNPB; i += 256)
        if (acc[i] != 0.f) atomicAdd(&dst[i], acc[i]);
}

// dinv = deg>0 ? rsqrt(deg) : 0 ;  u = dinv * x ;  zero g_S for k_sscat
__global__ void k_dinv(const float* __restrict__ x) {
    int i = blockIdx.x * blockDim.x + threadIdx.x;   // < BNODES
    float d  = g_deg[i];
    float dv = d > 0.f ? rsqrtf(d) : 0.f;
    g_dinv[i] = dv;
    g_u[i]    = dv * x[i];
    g_S[i]    = 0.f;
}

// S accumulation: val = ea * u[col], smem accumulate, coalesced RED merge
__global__ __launch_bounds__(256) void k_sscat() {
    __shared__ float acc[BNPB];     // 32 KB
    int b   = blockIdx.x / ACC_SPLIT;
    int q   = blockIdx.x % ACC_SPLIT;
    int tid = threadIdx.x;
    for (int i = tid; i < BNPB; i += 256) acc[i] = 0.f;
    __syncthreads();
    int n  = g_cursor[b];
    int e0 = (q * n) / ACC_SPLIT, e1 = ((q + 1) * n) / ACC_SPLIT;
    size_t bb = (size_t)b * BUCKCAP;
    for (int e = e0 + tid; e < e1; e += 256) {
        float v = s_ea[bb + e] * g_u[s_col[bb + e]];
        atomicAdd(&acc[s_lrow[bb + e]], v);
    }
    __syncthreads();
    float* dst = g_S + ((size_t)b << BSHIFT);
    for (int i = tid; i < BNPB; i += 256)
        if (acc[i] != 0.f) atomicAdd(&dst[i], acc[i]);
}

// fc1 GEMM with fused h construction (unchanged from passing R7 kernel)
__global__ __launch_bounds__(256) void k_fc1(
    const float* __restrict__ x,
    const float* __restrict__ W0, const float* __restrict__ W1,
    const float* __restrict__ cb, const float* __restrict__ fc1W) {

    __shared__ float h_s[128 * 64];
    int tid = threadIdx.x;
    int n0  = blockIdx.x * NODES_PER_BLK;

    float w0[COUT], w1[COUT], b8[COUT];
#pragma unroll
    for (int c = 0; c < COUT; c++) { w0[c] = W0[c]; w1[c] = W1[c]; b8[c] = cb[c]; }

#pragma unroll
    for (int p = 0; p < 4; p++) {
        int pi = p * 256 + tid;
        int b  = pi & 63;
        int nl = pi >> 6;
        int g  = b * NNODE + n0 + nl;
        float xv = x[g];
        float tv = -g_dinv[g] * g_S[g];
#pragma unroll
        for (int c = 0; c < COUT; c++) {
            float hv = fmaf(xv, w0[c], fmaf(tv, w1[c], b8[c]));
            h_s[(nl * COUT + c) * 64 + b] = lrelu(hv);
        }
    }
    __syncthreads();

    int dg = tid & 31;
    int bg = tid >> 5;

    unsigned long long acc[4][4];
#pragma unroll
    for (int p = 0; p < 4; p++)
#pragma unroll
        for (int j = 0; j < 4; j++) acc[p][j] = 0ull;

    const float4* Wp = (const float4*)fc1W + (size_t)n0 * COUT * (DIM / 4) + dg;

#pragma unroll 4
    for (int k = 0; k < NODES_PER_BLK * COUT; k++) {
        float4 w4 = __ldg(Wp + (size_t)k * (DIM / 4));
        float4 hA = *(const float4*)&h_s[k * 64 + bg * 8];
        float4 hB = *(const float4*)&h_s[k * 64 + bg * 8 + 4];

        unsigned long long hp0 = pk2(hA.x, hA.y);
        unsigned long long hp1 = pk2(hA.z, hA.w);
        unsigned long long hp2 = pk2(hB.x, hB.y);
        unsigned long long hp3 = pk2(hB.z, hB.w);
        unsigned long long wd0 = dup2(w4.x), wd1 = dup2(w4.y);
        unsigned long long wd2 = dup2(w4.z), wd3 = dup2(w4.w);

        fma2(acc[0][0], hp0, wd0); fma2(acc[0][1], hp0, wd1);
        fma2(acc[0][2], hp0, wd2); fma2(acc[0][3], hp0, wd3);
        fma2(acc[1][0], hp1, wd0); fma2(acc[1][1], hp1, wd1);
        fma2(acc[1][2], hp1, wd2); fma2(acc[1][3], hp1, wd3);
        fma2(acc[2][0], hp2, wd0); fma2(acc[2][1], hp2, wd1);
        fma2(acc[2][2], hp2, wd2); fma2(acc[2][3], hp2, wd3);
        fma2(acc[3][0], hp3, wd0); fma2(acc[3][1], hp3, wd1);
        fma2(acc[3][2], hp3, wd2); fma2(acc[3][3], hp3, wd3);
    }

    float* outp = g_part + (size_t)blockIdx.x * (BATCH * DIM);
#pragma unroll
    for (int p = 0; p < 4; p++) {
        float lo[4], hi[4];
#pragma unroll
        for (int j = 0; j < 4; j++) unpk2(acc[p][j], lo[j], hi[j]);
        int b0 = bg * 8 + p * 2;
        *(float4*)&outp[(b0 + 0) * DIM + dg * 4] = make_float4(lo[0], lo[1], lo[2], lo[3]);
        *(float4*)&outp[(b0 + 1) * DIM + dg * 4] = make_float4(hi[0], hi[1], hi[2], hi[3]);
    }
}

// reduce fc1 partials (two-level), add bias, lrelu
__global__ __launch_bounds__(256) void k_reduce(const float* __restrict__ fc1b) {
    __shared__ float red[8][32];
    int tid   = threadIdx.x;
    int slice = tid >> 5;
    int jl    = tid & 31;
    int j     = blockIdx.x * 32 + jl;

    const float* p = g_part + (size_t)(slice * (NB_FC1 / 8)) * (BATCH * DIM) + j;
    float s0 = 0.f, s1 = 0.f, s2 = 0.f, s3 = 0.f;
#pragma unroll 4
    for (int k = 0; k < NB_FC1 / 8; k += 4) {
        s0 += p[(size_t)(k + 0) * (BATCH * DIM)];
        s1 += p[(size_t)(k + 1) * (BATCH * DIM)];
        s2 += p[(size_t)(k + 2) * (BATCH * DIM)];
        s3 += p[(size_t)(k + 3) * (BATCH * DIM)];
    }
    red[slice][jl] = (s0 + s1) + (s2 + s3);
    __syncthreads();

    if (slice == 0) {
        float s = 0.f;
#pragma unroll
        for (int q = 0; q < 8; q++) s += red[q][jl];
        s += fc1b[j & (DIM - 1)];
        g_h1[j] = lrelu(s);
    }
}

// fc2 + lrelu + fc3
__global__ __launch_bounds__(DIM) void k_head(
    const float* __restrict__ fc2W, const float* __restrict__ fc2b,
    const float* __restrict__ fc3W, const float* __restrict__ fc3b,
    float* __restrict__ out) {
    __shared__ float h1s[DIM];
    __shared__ float h2s[DIM];
    int b = blockIdx.x, d = threadIdx.x;
    h1s[d] = g_h1[b * DIM + d];
    __syncthreads();
    float a = fc2b[d];
#pragma unroll 16
    for (int k = 0; k < DIM; k++) a = fmaf(h1s[k], fc2W[k * DIM + d], a);
    h2s[d] = lrelu(a);
    __syncthreads();
    if (d < BOUT) {
        float o = fc3b[d];
#pragma unroll 16
        for (int k = 0; k < DIM; k++) o = fmaf(h2s[k], fc3W[k * BOUT + d], o);
        out[b * BOUT + d] = o;
    }
}

// -------- launch --------
extern "C" void kernel_launch(void* const* d_in, const int* in_sizes, int n_in,
                              void* d_out, int out_size) {
    const float* x    = (const float*)d_in[0];
    const int*   ei   = (const int*)d_in[1];     // [2][EDGES] int32
    const float* ea   = (const float*)d_in[2];
    const float* W0   = (const float*)d_in[3];
    const float* W1   = (const float*)d_in[4];
    const float* cb   = (const float*)d_in[5];
    const float* fc1W = (const float*)d_in[6];
    const float* fc1b = (const float*)d_in[7];
    const float* fc2W = (const float*)d_in[8];
    const float* fc2b = (const float*)d_in[9];
    const float* fc3W = (const float*)d_in[10];
    const float* fc3b = (const float*)d_in[11];
    float* out = (float*)d_out;

    const int* row = ei;
    const int* col = ei + EDGES;

    k_init<<<BNODES / 4 / 256, 256>>>();
    k_sort<<<SORT_CTAS, 256>>>(row, col, ea);
    k_sdeg<<<ACC_CTAS, 256>>>();
    k_dinv<<<BNODES / 256, 256>>>(x);
    k_sscat<<<ACC_CTAS, 256>>>();
    k_fc1<<<NB_FC1, 256>>>(x, W0, W1, cb, fc1W);
    k_reduce<<<(BATCH * DIM) / 32, 256>>>(fc1b);
    k_head<<<BATCH, DIM>>>(fc2W, fc2b, fc3W, fc3b, out);
}